// round 17
// baseline (speedup 1.0000x reference)
#include <cuda_runtime.h>
#include <cuda_fp16.h>
#include <math.h>

// ---------------------------------------------------------------------------
// Problem constants
// ---------------------------------------------------------------------------
#define BATCH   16384
#define LSEQ    200
#define CONCAT  244
#define KPAD    256
#define NEXP    8
#define EHID    256
#define EOUT    128
#define NTASK   2
#define NITEMS1 100001
#define CH      32
#define NCH     7
#define SEQPAD  224
#define HLD2    72
#define LLD     68

// ---------------------------------------------------------------------------
// Scratch (static device globals — no allocation allowed)
// ---------------------------------------------------------------------------
__device__ float  g_S   [(long)BATCH * CONCAT];
__device__ __half g_Sh  [(long)BATCH * KPAD];
__device__ __half g_ehh [(long)NEXP * BATCH * EHID];
__device__ __half g_eo  [(long)NEXP * BATCH * EOUT];
__device__ __half g_W1t [(long)NEXP * EHID * KPAD];
__device__ __half g_W2t [(long)NEXP * EOUT * KPAD];
__device__ __half g_t16 [(long)BATCH * 64];
__device__ float  g_base[(long)BATCH * 64];
__device__ __half g_hist16[(long)NITEMS1 * 64];
__device__ __half g_Pt  [64 * 64];
__device__ __half g_W3t [64 * 64];
__device__ __half g_aW2t[16 * 64];
__device__ float  g_Wb  [64 * 64];

// ---------------------------------------------------------------------------
// cp.async / ldmatrix / mma helpers
// ---------------------------------------------------------------------------
__device__ __forceinline__ void cp_async16(void* smem_dst, const void* gsrc) {
    unsigned sm = (unsigned)__cvta_generic_to_shared(smem_dst);
    asm volatile("cp.async.cg.shared.global [%0], [%1], 16;\n" :: "r"(sm), "l"(gsrc));
}
__device__ __forceinline__ void cp_commit() {
    asm volatile("cp.async.commit_group;\n");
}
template <int N>
__device__ __forceinline__ void cp_wait() {
    asm volatile("cp.async.wait_group %0;\n" :: "n"(N));
}
__device__ __forceinline__ void cp_wait_n(int n) {
    switch (n) {
        case 0: cp_wait<0>(); break;
        case 1: cp_wait<1>(); break;
        case 2: cp_wait<2>(); break;
        case 3: cp_wait<3>(); break;
        case 4: cp_wait<4>(); break;
        case 5: cp_wait<5>(); break;
        case 6: cp_wait<6>(); break;
        default: cp_wait<7>(); break;
    }
}

__device__ __forceinline__ void ldsm_x4(unsigned* r, const void* p) {
    unsigned addr = (unsigned)__cvta_generic_to_shared(p);
    asm volatile("ldmatrix.sync.aligned.m8n8.x4.shared.b16 {%0,%1,%2,%3}, [%4];\n"
                 : "=r"(r[0]), "=r"(r[1]), "=r"(r[2]), "=r"(r[3]) : "r"(addr));
}

__device__ __forceinline__ void mma_f16(float* d, const unsigned* a, const unsigned* b) {
    asm volatile(
        "mma.sync.aligned.m16n8k16.row.col.f32.f16.f16.f32 "
        "{%0,%1,%2,%3}, {%4,%5,%6,%7}, {%8,%9}, {%0,%1,%2,%3};\n"
        : "+f"(d[0]), "+f"(d[1]), "+f"(d[2]), "+f"(d[3])
        : "r"(a[0]), "r"(a[1]), "r"(a[2]), "r"(a[3]),
          "r"(b[0]), "r"(b[1]));
}

// ---------------------------------------------------------------------------
// Kernel 0: weight prep
// ---------------------------------------------------------------------------
#define N_W1T (NEXP * EHID * KPAD)
#define N_W2T (NEXP * EOUT * KPAD)
#define N_PT  (64 * 64)
#define N_W3  (64 * 64)
#define N_AW2 (16 * 64)
#define N_WB  (64 * 64)
#define N_PREP (N_W1T + N_W2T + N_PT + N_W3 + N_AW2 + N_WB)

__global__ void __launch_bounds__(256)
prep_weights(const float* __restrict__ eW1, const float* __restrict__ eW2,
             const float* __restrict__ aW1, const float* __restrict__ aW2,
             __half* __restrict__ W1t, __half* __restrict__ W2t,
             __half* __restrict__ Pt, __half* __restrict__ W3t,
             __half* __restrict__ aW2t, float* __restrict__ Wb)
{
    int i = blockIdx.x * 256 + threadIdx.x;
    if (i < N_W1T) {
        const int e = i >> 16, n = (i >> 8) & 255, k = i & 255;
        const float v = (k < CONCAT) ? eW1[((long)e * CONCAT + k) * EHID + n] : 0.f;
        W1t[i] = __float2half(v);
        return;
    }
    i -= N_W1T;
    if (i < N_W2T) {
        const int e = i >> 15, n = (i >> 8) & 127, k = i & 255;
        W2t[i] = __float2half(eW2[((long)e * EHID + k) * EOUT + n]);
        return;
    }
    i -= N_W2T;
    if (i < N_PT) {
        const int n = i >> 6, k = i & 63;
        Pt[i] = __float2half(aW1[(64 + k) * 64 + n] - aW1[(128 + k) * 64 + n]);
        return;
    }
    i -= N_PT;
    if (i < N_W3) {
        const int n = i >> 6, k = i & 63;
        W3t[i] = __float2half(aW1[(192 + k) * 64 + n]);
        return;
    }
    i -= N_W3;
    if (i < N_AW2) {
        const int n = i >> 6, k = i & 63;
        aW2t[i] = __float2half(aW2[k * 16 + n]);
        return;
    }
    i -= N_AW2;
    if (i < N_WB) {
        const int k = i >> 6, j = i & 63;
        Wb[i] = aW1[k * 64 + j] + aW1[(128 + k) * 64 + j];
    }
}

// ---------------------------------------------------------------------------
// Kernel 0c: convert histE to fp16
// ---------------------------------------------------------------------------
#define N_HIST2 ((long)NITEMS1 * 32)

__global__ void __launch_bounds__(256)
conv_hist(const float* __restrict__ histE, __half* __restrict__ h16)
{
    const long i = (long)blockIdx.x * 256 + threadIdx.x;
    if (i < N_HIST2) {
        const float2 v = reinterpret_cast<const float2*>(histE)[i];
        reinterpret_cast<__half2*>(h16)[i] = __floats2half2_rn(v.x, v.y);
    }
}

// ---------------------------------------------------------------------------
// Kernel 0b: per-row t = i_emb @ Wproj (fp16) and base = ab1 + t @ Wb
// ---------------------------------------------------------------------------
struct TBSmem {
    float Wp[64 * LLD];
    float Wbs[64 * LLD];
    float I[64 * LLD];
    float T[64 * LLD];
    int   ids[64];
};

__global__ void __launch_bounds__(256)
tbase_kernel(const int* __restrict__ iid, const float* __restrict__ itemE,
             const float* __restrict__ Wproj, const float* __restrict__ Wb,
             const float* __restrict__ ab1,
             __half* __restrict__ t16, float* __restrict__ base)
{
    extern __shared__ unsigned char smem_raw[];
    TBSmem& s = *reinterpret_cast<TBSmem*>(smem_raw);
    const int tid = threadIdx.x;
    const int b0 = blockIdx.x * 64;

    if (tid < 64) s.ids[tid] = iid[b0 + tid];
    #pragma unroll
    for (int h = 0; h < 4; h++) {
        const int idx = tid + h * 256;
        const int k = idx >> 4, f = (idx & 15) * 4;
        cp_async16(&s.Wp[k * LLD + f],  Wproj + k * 64 + f);
        cp_async16(&s.Wbs[k * LLD + f], Wb    + k * 64 + f);
    }
    cp_commit();
    __syncthreads();
    #pragma unroll
    for (int h = 0; h < 4; h++) {
        const int idx = tid + h * 256;
        const int r = idx >> 4, f = (idx & 15) * 4;
        cp_async16(&s.I[r * LLD + f], itemE + (long)s.ids[r] * 64 + f);
    }
    cp_commit();
    cp_wait<0>();
    __syncthreads();

    const int r = tid >> 2;
    const int jg = (tid & 3) * 16;
    {
        float acc[16];
        #pragma unroll
        for (int j = 0; j < 16; j++) acc[j] = 0.f;
        #pragma unroll 4
        for (int k = 0; k < 64; k++) {
            const float ik = s.I[r * LLD + k];
            #pragma unroll
            for (int j = 0; j < 16; j++) acc[j] += ik * s.Wp[k * LLD + jg + j];
        }
        #pragma unroll
        for (int j = 0; j < 16; j++) {
            s.T[r * LLD + jg + j] = acc[j];
            t16[(long)(b0 + r) * 64 + jg + j] = __float2half(acc[j]);
        }
    }
    __syncthreads();
    {
        float acc[16];
        #pragma unroll
        for (int j = 0; j < 16; j++) acc[j] = ab1[jg + j];
        #pragma unroll 4
        for (int k = 0; k < 64; k++) {
            const float tk = s.T[r * LLD + k];
            #pragma unroll
            for (int j = 0; j < 16; j++) acc[j] += tk * s.Wbs[k * LLD + jg + j];
        }
        #pragma unroll
        for (int j = 0; j < 16; j++)
            base[(long)(b0 + r) * 64 + jg + j] = acc[j];
    }
}

// ---------------------------------------------------------------------------
// Kernel 1: DIN attention — fused M, phase-paired chunks, pooling overlap,
// gathers issued pre-barrier from direct LDG seq ids, 9 barriers total.
// ---------------------------------------------------------------------------
struct AttnSmem {
    __half h[SEQPAD * HLD2];
    __half h1[2][CH * HLD2];       // tail: aliased as float scratch
    __half Mt[64 * HLD2];
    __half aW2t[16 * HLD2];
    __half2 t2s[32];
    float base[64];
    float sc[SEQPAD];
    float aW3s[16];
    float ab2s[16];
    float red[8];
    float denom;
    int   seqs[SEQPAD];
};

__global__ void __launch_bounds__(256, 4)
attn_kernel(const int* __restrict__ uid, const int* __restrict__ iid,
            const int* __restrict__ cid, const int* __restrict__ did,
            const float* __restrict__ udense, const float* __restrict__ idense,
            const int* __restrict__ hseq,
            const float* __restrict__ userE, const float* __restrict__ itemE,
            const float* __restrict__ catE,  const float* __restrict__ durE,
            const __half* __restrict__ hist16,
            const __half* __restrict__ t16, const float* __restrict__ baseg,
            const __half* __restrict__ Ptg, const __half* __restrict__ W3tg,
            const __half* __restrict__ aW2tg,
            const float* __restrict__ aW3, const float* __restrict__ ab3,
            const float* __restrict__ ab2,
            float* __restrict__ Sout, __half* __restrict__ Shout)
{
    extern __shared__ unsigned char smem_raw[];
    AttnSmem& s = *reinterpret_cast<AttnSmem*>(smem_raw);

    const int b    = blockIdx.x;
    const int tid  = threadIdx.x;
    const int lane = tid & 31;
    const int warp = tid >> 5;
    const int qr   = lane >> 2;
    const int qc   = lane & 3;

    // ---- group 0: stage aW2t ----
    if (tid < 128) {
        const int n = tid >> 3, k8 = (tid & 7) * 8;
        cp_async16(&s.aW2t[n * HLD2 + k8], aW2tg + n * 64 + k8);
    }
    cp_commit();

    // ---- groups 1..7: chunk gathers issued IMMEDIATELY from direct LDG ids
    //      (8 threads share one id -> L1 broadcast); smem seqs staged in
    //      parallel for the mask/exp consumers (first used after sync#2).
    {
        const int r = tid >> 3;                   // 0..31
        const int f8 = (tid & 7) * 8;
        const long hrow = (long)b * LSEQ;
        #pragma unroll
        for (int ch = 0; ch < NCH; ch++) {
            const int l = ch * CH + r;
            const int sid = (l < LSEQ) ? __ldg(hseq + hrow + l) : 0;
            cp_async16(&s.h[(ch * CH + r) * HLD2 + f8], hist16 + (long)sid * 64 + f8);
            cp_commit();
        }
    }

    // ---- per-row constants + sequence ids (parallel with gathers) ----
    if (tid < 32)
        s.t2s[tid] = reinterpret_cast<const __half2*>(t16 + (long)b * 64)[tid];
    if (tid < 64) s.base[tid] = baseg[(long)b * 64 + tid];
    if (tid < 16) { s.aW3s[tid] = aW3[tid]; s.ab2s[tid] = ab2[tid]; }
    if (tid < SEQPAD) s.seqs[tid] = (tid < LSEQ) ? hseq[(long)b * LSEQ + tid] : 0;
    __syncthreads();    // t2s visible for Mt build; seqs/base published

    // ---- build fused M^T[n][k] = Pt + t[k]*W3t ----
    for (int i = tid; i < 64 * 32; i += 256) {
        const int n = i >> 5, k2 = i & 31;
        const __half2 p = *reinterpret_cast<const __half2*>(Ptg  + n * 64 + 2 * k2);
        const __half2 w = *reinterpret_cast<const __half2*>(W3tg + n * 64 + 2 * k2);
        *reinterpret_cast<__half2*>(&s.Mt[n * HLD2 + 2 * k2]) = __hfma2(s.t2s[k2], w, p);
    }
    __syncthreads();

    const int wm = warp & 1;
    const int wn = warp >> 1;
    unsigned bM[4][2][2];
    #pragma unroll
    for (int ks = 0; ks < 4; ks++)
        #pragma unroll
        for (int ni = 0; ni < 2; ni++) {
            const __half* bp = &s.Mt[(wn * 16 + ni * 8 + qr) * HLD2 + ks * 16 + 2 * qc];
            bM[ks][ni][0] = *reinterpret_cast<const unsigned*>(bp);
            bM[ks][ni][1] = *reinterpret_cast<const unsigned*>(bp + 8);
        }

    const float ab3v = ab3[0];
    const int lrow = (lane & 7) + ((lane >> 3) & 1) * 8;
    const int lkof = (lane >> 4) * 8;

    float pax = 0.f, pay = 0.f;   // pooling partials (warps 4-7)

    // ---- phase loop: 2 chunks per phase, 2 barriers per phase ----
    #pragma unroll
    for (int p = 0; p < 4; p++) {
        const int c0v = 2 * p;
        const bool has2 = (p < 3);
        cp_wait_n(has2 ? (NCH - 2 - c0v) : 0);
        __syncthreads();     // also orders prior phase's h1 reads vs writes below

        // layer 1 for both chunks of the phase (all 8 warps)
        {
            const int n8 = wn * 16;
            #pragma unroll
            for (int j = 0; j < 2; j++) {
                if (j == 1 && !has2) break;
                const int cc = c0v + j;
                float acc[2][4];
                #pragma unroll
                for (int ni = 0; ni < 2; ni++) {
                    const int nn = n8 + ni * 8;
                    acc[ni][0] = s.base[nn + 2 * qc];
                    acc[ni][1] = s.base[nn + 2 * qc + 1];
                    acc[ni][2] = acc[ni][0];
                    acc[ni][3] = acc[ni][1];
                }
                const int rowb = cc * CH + wm * 16;
                #pragma unroll
                for (int ks = 0; ks < 4; ks++) {
                    unsigned a[4];
                    ldsm_x4(a, &s.h[(rowb + lrow) * HLD2 + ks * 16 + lkof]);
                    mma_f16(acc[0], a, bM[ks][0]);
                    mma_f16(acc[1], a, bM[ks][1]);
                }
                __half* h1b = s.h1[j];
                const int rr = wm * 16 + qr;
                #pragma unroll
                for (int ni = 0; ni < 2; ni++) {
                    const int nn = n8 + ni * 8;
                    *reinterpret_cast<__half2*>(&h1b[rr * HLD2 + nn + 2 * qc]) =
                        __floats2half2_rn(fmaxf(acc[ni][0], 0.f), fmaxf(acc[ni][1], 0.f));
                    *reinterpret_cast<__half2*>(&h1b[(rr + 8) * HLD2 + nn + 2 * qc]) =
                        __floats2half2_rn(fmaxf(acc[ni][2], 0.f), fmaxf(acc[ni][3], 0.f));
                }
            }
        }
        __syncthreads();

        // warps 0-3: layer 2+3 for this phase ; warps 4-7: pooling for p-1
        const int nlw = has2 ? 4 : 2;
        if (warp < nlw) {
            const int j  = warp >> 1;
            const int cc = c0v + j;
            const int wr16 = (warp & 1) * 16;
            const __half* h1b = s.h1[j];
            float acc2[2][4];
            #pragma unroll
            for (int ni = 0; ni < 2; ni++) {
                acc2[ni][0] = s.ab2s[ni * 8 + 2 * qc];
                acc2[ni][1] = s.ab2s[ni * 8 + 2 * qc + 1];
                acc2[ni][2] = acc2[ni][0];
                acc2[ni][3] = acc2[ni][1];
            }
            #pragma unroll
            for (int ks = 0; ks < 4; ks++) {
                unsigned a[4];
                ldsm_x4(a, &h1b[(wr16 + lrow) * HLD2 + ks * 16 + lkof]);
                #pragma unroll
                for (int ni = 0; ni < 2; ni++) {
                    unsigned bv[2];
                    const __half* bp = &s.aW2t[(ni * 8 + qr) * HLD2 + ks * 16 + 2 * qc];
                    bv[0] = *reinterpret_cast<const unsigned*>(bp);
                    bv[1] = *reinterpret_cast<const unsigned*>(bp + 8);
                    mma_f16(acc2[ni], a, bv);
                }
            }
            float w0 = 0.f, w1 = 0.f;
            #pragma unroll
            for (int ni = 0; ni < 2; ni++) {
                const float g0 = s.aW3s[ni * 8 + 2 * qc];
                const float g1 = s.aW3s[ni * 8 + 2 * qc + 1];
                w0 += fmaxf(acc2[ni][0], 0.f) * g0 + fmaxf(acc2[ni][1], 0.f) * g1;
                w1 += fmaxf(acc2[ni][2], 0.f) * g0 + fmaxf(acc2[ni][3], 0.f) * g1;
            }
            w0 += __shfl_xor_sync(0xffffffffu, w0, 1);
            w0 += __shfl_xor_sync(0xffffffffu, w0, 2);
            w1 += __shfl_xor_sync(0xffffffffu, w1, 1);
            w1 += __shfl_xor_sync(0xffffffffu, w1, 2);
            if (qc == 0) {
                const int l0 = cc * CH + wr16 + qr;
                const int l1 = l0 + 8;
                float e0 = 0.f, e1 = 0.f;
                if (l0 < LSEQ && s.seqs[l0] != 0) e0 = __expf(w0 + ab3v);
                if (l1 < LSEQ && s.seqs[l1] != 0) e1 = __expf(w1 + ab3v);
                s.sc[l0] = e0;
                s.sc[l1] = e1;
            }
        } else if (warp >= 4 && p > 0) {
            const int rbase = (p - 1) * 64 + (warp - 4) * 16;
            #pragma unroll
            for (int i = 0; i < 16; i++) {
                const int l = rbase + i;
                const float w = s.sc[l];
                const __half2 hv = *reinterpret_cast<const __half2*>(&s.h[l * HLD2 + 2 * lane]);
                pax += w * __low2float(hv);
                pay += w * __high2float(hv);
            }
        }
        // NOTE: no phase-end barrier — next phase's top barrier provides the
        // ordering (no smem access occurs in between).
    }
    __syncthreads();   // phase-3 sc writes visible for tail pooling + denom

    // ---- tail pooling: rows 192..223, warps 4-7 ----
    if (warp >= 4) {
        const int rbase = 192 + (warp - 4) * 8;
        #pragma unroll
        for (int i = 0; i < 8; i++) {
            const int l = rbase + i;
            const float w = s.sc[l];
            const __half2 hv = *reinterpret_cast<const __half2*>(&s.h[l * HLD2 + 2 * lane]);
            pax += w * __low2float(hv);
            pay += w * __high2float(hv);
        }
    }

    // ---- denom = sum sc ----
    {
        float sv = (tid < SEQPAD) ? s.sc[tid] : 0.f;
        #pragma unroll
        for (int off = 16; off >= 1; off >>= 1)
            sv += __shfl_xor_sync(0xffffffffu, sv, off);
        if (lane == 0) s.red[warp] = sv;
    }
    __syncthreads();
    if (tid == 0) {
        float ss = 0.f;
        #pragma unroll
        for (int w = 0; w < 8; w++) ss += s.red[w];
        s.denom = 1.f / ss;
    }

    // ---- combine pooling partials (scratch aliased onto dead h1) ----
    float* part4   = reinterpret_cast<float*>(s.h1);
    float* poolred = part4 + 4 * 64;
    if (warp >= 4) {
        part4[(warp - 4) * 64 + 2 * lane]     = pax;
        part4[(warp - 4) * 64 + 2 * lane + 1] = pay;
    }
    __syncthreads();
    if (tid < 64) {
        float acc = 0.f;
        #pragma unroll
        for (int g = 0; g < 4; g++) acc += part4[g * 64 + tid];
        poolred[tid] = acc * s.denom;
    }
    __syncthreads();

    // ---- write feature row (fp32 + fp16 padded) ----
    {
        const int item = iid[b];
        float v = 0.f;
        if (tid < CONCAT) {
            if      (tid < 64)  v = userE[(long)uid[b] * 64 + tid];
            else if (tid < 128) v = itemE[(long)item * 64 + (tid - 64)];
            else if (tid < 144) v = catE[(long)cid[b] * 16 + (tid - 128)];
            else if (tid < 152) v = durE[(long)did[b] * 8 + (tid - 144)];
            else if (tid < 177) v = udense[(long)b * 25 + (tid - 152)];
            else if (tid < 180) v = idense[(long)b * 3 + (tid - 177)];
            else                v = poolred[tid - 180];
            Sout[(long)b * CONCAT + tid] = v;
        }
        Shout[(long)b * KPAD + tid] = __float2half(v);
    }
}

// ---------------------------------------------------------------------------
// Kernel 2: batched fp16 GEMM + bias + ReLU — ldmatrix operand loads
// ---------------------------------------------------------------------------
#define TBM 128
#define TBN 128
#define TBK 16
#define NSTG 4
#define HLG 24

#define HGEMM_SMEM ((NSTG * TBM * HLG + NSTG * TBN * HLG) * 2)

template <bool OUT_HALF>
__global__ void __launch_bounds__(256, 2)
hgemm_bias_relu(const __half* __restrict__ A, const __half* __restrict__ Bt,
                const float* __restrict__ bias, void* __restrict__ Cout,
                int M, int N,
                size_t sA, size_t sB, size_t sBias, size_t sC)
{
    extern __shared__ __half smemh[];
    __half* As = smemh;
    __half* Bs = smemh + NSTG * TBM * HLG;

    const int z = blockIdx.z;
    A += (size_t)z * sA; Bt += (size_t)z * sB;
    bias += (size_t)z * sBias;

    const int m0 = blockIdx.y * TBM;
    const int n0 = blockIdx.x * TBN;
    const int tid = threadIdx.x;
    const int lane = tid & 31;
    const int warp = tid >> 5;
    const int wr = warp >> 2;
    const int wc = warp & 3;
    const int qr = lane >> 2;
    const int qc = lane & 3;
    const int lrow = (lane & 7) + ((lane >> 3) & 1) * 8;
    const int lkof = (lane >> 4) * 8;

    const int nk = KPAD / TBK;

    const int l_row = tid >> 1;
    const int l_hc  = (tid & 1) * 8;

    auto load_stage = [&](int st, int k0) {
        __half* as = As + st * TBM * HLG;
        __half* bs = Bs + st * TBN * HLG;
        cp_async16(&as[l_row * HLG + l_hc], A  + (size_t)(m0 + l_row) * KPAD + k0 + l_hc);
        cp_async16(&bs[l_row * HLG + l_hc], Bt + (size_t)(n0 + l_row) * KPAD + k0 + l_hc);
    };

    float acc[4][4][4];
    #pragma unroll
    for (int i = 0; i < 4; i++)
        #pragma unroll
        for (int j = 0; j < 4; j++)
            #pragma unroll
            for (int e = 0; e < 4; e++) acc[i][j][e] = 0.f;

    #pragma unroll
    for (int s0 = 0; s0 < NSTG - 1; s0++) {
        load_stage(s0, s0 * TBK);
        cp_commit();
    }

    for (int kt = 0; kt < nk; kt++) {
        cp_wait<NSTG - 2>();
        __syncthreads();

        const int knext = kt + NSTG - 1;
        if (knext < nk) load_stage(knext % NSTG, knext * TBK);
        cp_commit();

        const __half* as = As + (kt % NSTG) * TBM * HLG;
        const __half* bs = Bs + (kt % NSTG) * TBN * HLG;

        unsigned a[4][4], bfr[4][2];
        #pragma unroll
        for (int mi = 0; mi < 4; mi++)
            ldsm_x4(a[mi], &as[(wr * 64 + mi * 16 + lrow) * HLG + lkof]);
        #pragma unroll
        for (int nj = 0; nj < 2; nj++) {
            unsigned t4[4];
            ldsm_x4(t4, &bs[(wc * 32 + nj * 16 + lrow) * HLG + lkof]);
            bfr[nj * 2][0]     = t4[0];
            bfr[nj * 2][1]     = t4[2];
            bfr[nj * 2 + 1][0] = t4[1];
            bfr[nj * 2 + 1][1] = t4[3];
        }
        #pragma unroll
        for (int mi = 0; mi < 4; mi++)
            #pragma unroll
            for (int ni = 0; ni < 4; ni++)
                mma_f16(acc[mi][ni], a[mi], bfr[ni]);

        __syncthreads();
    }

    #pragma unroll
    for (int mi = 0; mi < 4; mi++) {
        #pragma unroll
        for (int ni = 0; ni < 4; ni++) {
            const int gm = m0 + wr * 64 + mi * 16 + qr;
            const int gn = n0 + wc * 32 + ni * 8 + qc * 2;
            const float b0 = bias[gn], b1 = bias[gn + 1];
            const float v0 = fmaxf(acc[mi][ni][0] + b0, 0.f);
            const float v1 = fmaxf(acc[mi][ni][1] + b1, 0.f);
            const float v2 = fmaxf(acc[mi][ni][2] + b0, 0.f);
            const float v3 = fmaxf(acc[mi][ni][3] + b1, 0.f);
            if (OUT_HALF) {
                __half* C = (__half*)Cout + (size_t)z * sC;
                *reinterpret_cast<__half2*>(C + (size_t)gm * N + gn) =
                    __floats2half2_rn(v0, v1);
                *reinterpret_cast<__half2*>(C + (size_t)(gm + 8) * N + gn) =
                    __floats2half2_rn(v2, v3);
            } else {
                float* C = (float*)Cout + (size_t)z * sC;
                *reinterpret_cast<float2*>(C + (size_t)gm * N + gn) = make_float2(v0, v1);
                *reinterpret_cast<float2*>(C + (size_t)(gm + 8) * N + gn) = make_float2(v2, v3);
            }
        }
    }
}

// ---------------------------------------------------------------------------
// Kernel 3: gates + mix + towers + sigmoid (eo fp16, 4-way ILP)
// ---------------------------------------------------------------------------
__global__ void __launch_bounds__(256)
head_kernel(const float* __restrict__ S, const __half* __restrict__ eo,
            const float* __restrict__ gW, const float* __restrict__ gb,
            const float* __restrict__ tW1, const float* __restrict__ tb1,
            const float* __restrict__ tW2, const float* __restrict__ tb2,
            const float* __restrict__ tW3, const float* __restrict__ tb3,
            float* __restrict__ out)
{
    __shared__ float Srow[4][CONCAT];
    __shared__ float gate[4][16];
    __shared__ float ti[4][NTASK][EOUT];
    __shared__ float x1[4][NTASK][64];
    __shared__ float x2[4][NTASK][32];

    const int g = threadIdx.x >> 6;
    const int lane = threadIdx.x & 63;
    const int b = blockIdx.x * 4 + g;

    for (int c = lane; c < CONCAT; c += 64) Srow[g][c] = S[(long)b * CONCAT + c];
    __syncthreads();

    {
        const int o = lane >> 2;
        const int q = lane & 3;
        const int t = o >> 3, e = o & 7;
        const int c0 = q * 61;
        float a0 = 0.f, a1 = 0.f, a2 = 0.f, a3 = 0.f;
        #pragma unroll
        for (int i = 0; i < 60; i += 4) {
            a0 += Srow[g][c0 + i]     * __ldg(&gW[((long)t * CONCAT + c0 + i)     * 8 + e]);
            a1 += Srow[g][c0 + i + 1] * __ldg(&gW[((long)t * CONCAT + c0 + i + 1) * 8 + e]);
            a2 += Srow[g][c0 + i + 2] * __ldg(&gW[((long)t * CONCAT + c0 + i + 2) * 8 + e]);
            a3 += Srow[g][c0 + i + 3] * __ldg(&gW[((long)t * CONCAT + c0 + i + 3) * 8 + e]);
        }
        a0 += Srow[g][c0 + 60] * __ldg(&gW[((long)t * CONCAT + c0 + 60) * 8 + e]);
        float acc = (a0 + a1) + (a2 + a3);
        acc += __shfl_xor_sync(0xffffffffu, acc, 1);
        acc += __shfl_xor_sync(0xffffffffu, acc, 2);
        if (q == 0) gate[g][o] = acc + gb[t * 8 + e];
    }
    __syncthreads();
    if (lane < 2) {
        const int t = lane;
        float mx = -3.4e38f;
        for (int e = 0; e < 8; e++) mx = fmaxf(mx, gate[g][t * 8 + e]);
        float sum = 0.f, ex[8];
        for (int e = 0; e < 8; e++) { ex[e] = __expf(gate[g][t * 8 + e] - mx); sum += ex[e]; }
        const float is = 1.f / sum;
        for (int e = 0; e < 8; e++) gate[g][t * 8 + e] = ex[e] * is;
    }
    __syncthreads();

    {
        const int t = lane >> 5;
        const int o = (lane & 31) * 4;
        float4 acc = make_float4(0.f, 0.f, 0.f, 0.f);
        #pragma unroll
        for (int e = 0; e < 8; e++) {
            const float gv = gate[g][t * 8 + e];
            const __half2* ep = reinterpret_cast<const __half2*>(
                eo + ((long)e * BATCH + b) * EOUT + o);
            const __half2 v01 = ep[0], v23 = ep[1];
            acc.x += gv * __low2float(v01);
            acc.y += gv * __high2float(v01);
            acc.z += gv * __low2float(v23);
            acc.w += gv * __high2float(v23);
        }
        *reinterpret_cast<float4*>(&ti[g][t][o]) = acc;
    }
    __syncthreads();

    for (int idx = lane; idx < NTASK * 64; idx += 64) {
        const int t = idx >> 6, j = idx & 63;
        float a0 = tb1[t * 64 + j], a1 = 0.f, a2 = 0.f, a3 = 0.f;
        #pragma unroll
        for (int o = 0; o < 128; o += 4) {
            a0 += ti[g][t][o]     * __ldg(&tW1[((long)t * 128 + o)     * 64 + j]);
            a1 += ti[g][t][o + 1] * __ldg(&tW1[((long)t * 128 + o + 1) * 64 + j]);
            a2 += ti[g][t][o + 2] * __ldg(&tW1[((long)t * 128 + o + 2) * 64 + j]);
            a3 += ti[g][t][o + 3] * __ldg(&tW1[((long)t * 128 + o + 3) * 64 + j]);
        }
        x1[g][t][j] = fmaxf((a0 + a1) + (a2 + a3), 0.f);
    }
    __syncthreads();

    {
        const int t = lane >> 5, m = lane & 31;
        float a0 = tb2[t * 32 + m], a1 = 0.f, a2 = 0.f, a3 = 0.f;
        #pragma unroll
        for (int j = 0; j < 64; j += 4) {
            a0 += x1[g][t][j]     * __ldg(&tW2[(t * 64 + j)     * 32 + m]);
            a1 += x1[g][t][j + 1] * __ldg(&tW2[(t * 64 + j + 1) * 32 + m]);
            a2 += x1[g][t][j + 2] * __ldg(&tW2[(t * 64 + j + 2) * 32 + m]);
            a3 += x1[g][t][j + 3] * __ldg(&tW2[(t * 64 + j + 3) * 32 + m]);
        }
        x2[g][t][m] = fmaxf((a0 + a1) + (a2 + a3), 0.f);
    }
    __syncthreads();

    if (lane < 2) {
        const int t = lane;
        float a0 = tb3[t], a1 = 0.f, a2 = 0.f, a3 = 0.f;
        #pragma unroll
        for (int m = 0; m < 32; m += 4) {
            a0 += x2[g][t][m]     * tW3[t * 32 + m];
            a1 += x2[g][t][m + 1] * tW3[t * 32 + m + 1];
            a2 += x2[g][t][m + 2] * tW3[t * 32 + m + 2];
            a3 += x2[g][t][m + 3] * tW3[t * 32 + m + 3];
        }
        const float acc = (a0 + a1) + (a2 + a3);
        out[(long)t * BATCH + b] = 1.f / (1.f + __expf(-acc));
    }
}

// ---------------------------------------------------------------------------
// Launch
// ---------------------------------------------------------------------------
extern "C" void kernel_launch(void* const* d_in, const int* in_sizes, int n_in,
                              void* d_out, int out_size)
{
    const int*   uid    = (const int*)  d_in[0];
    const int*   iid    = (const int*)  d_in[1];
    const int*   cid    = (const int*)  d_in[2];
    const int*   did    = (const int*)  d_in[3];
    const float* udense = (const float*)d_in[4];
    const float* idense = (const float*)d_in[5];
    const int*   hseq   = (const int*)  d_in[6];
    const float* userE  = (const float*)d_in[7];
    const float* itemE  = (const float*)d_in[8];
    const float* catE   = (const float*)d_in[9];
    const float* durE   = (const float*)d_in[10];
    const float* histE  = (const float*)d_in[11];
    const float* Wproj  = (const float*)d_in[12];
    const float* aW1    = (const float*)d_in[13];
    const float* ab1    = (const float*)d_in[14];
    const float* aW2    = (const float*)d_in[15];
    const float* ab2    = (const float*)d_in[16];
    const float* aW3    = (const float*)d_in[17];
    const float* ab3    = (const float*)d_in[18];
    const float* eW1    = (const float*)d_in[19];
    const float* eb1    = (const float*)d_in[20];
    const float* eW2    = (const float*)d_in[21];
    const float* eb2    = (const float*)d_in[22];
    const float* gW     = (const float*)d_in[23];
    const float* gb     = (const float*)d_in[24];
    const float* tW1    = (const float*)d_in[25];
    const float* tb1    = (const float*)d_in[26];
    const float* tW2    = (const float*)d_in[27];
    const float* tb2    = (const float*)d_in[28];
    const float* tW3    = (const float*)d_in[29];
    const float* tb3    = (const float*)d_in[30];
    float* out = (float*)d_out;

    float  *pS, *pBase, *pWb;
    __half *pSh, *pEh, *pEo, *pW1t, *pW2t, *pT16, *pPt, *pW3t, *pAW2t, *pH16;
    cudaGetSymbolAddress((void**)&pS,    g_S);
    cudaGetSymbolAddress((void**)&pSh,   g_Sh);
    cudaGetSymbolAddress((void**)&pEh,   g_ehh);
    cudaGetSymbolAddress((void**)&pEo,   g_eo);
    cudaGetSymbolAddress((void**)&pW1t,  g_W1t);
    cudaGetSymbolAddress((void**)&pW2t,  g_W2t);
    cudaGetSymbolAddress((void**)&pT16,  g_t16);
    cudaGetSymbolAddress((void**)&pBase, g_base);
    cudaGetSymbolAddress((void**)&pPt,   g_Pt);
    cudaGetSymbolAddress((void**)&pW3t,  g_W3t);
    cudaGetSymbolAddress((void**)&pAW2t, g_aW2t);
    cudaGetSymbolAddress((void**)&pWb,   g_Wb);
    cudaGetSymbolAddress((void**)&pH16,  g_hist16);

    const int attn_smem = (int)sizeof(AttnSmem);
    const int tb_smem   = (int)sizeof(TBSmem);
    cudaFuncSetAttribute(attn_kernel,  cudaFuncAttributeMaxDynamicSharedMemorySize, attn_smem);
    cudaFuncSetAttribute(tbase_kernel, cudaFuncAttributeMaxDynamicSharedMemorySize, tb_smem);
    cudaFuncSetAttribute(hgemm_bias_relu<true>,  cudaFuncAttributeMaxDynamicSharedMemorySize, HGEMM_SMEM);
    cudaFuncSetAttribute(hgemm_bias_relu<false>, cudaFuncAttributeMaxDynamicSharedMemorySize, HGEMM_SMEM);

    // K0: weight prep + history fp16 conversion + per-row t/base
    prep_weights<<<(N_PREP + 255) / 256, 256>>>(
        eW1, eW2, aW1, aW2, pW1t, pW2t, pPt, pW3t, pAW2t, pWb);
    conv_hist<<<(int)((N_HIST2 + 255) / 256), 256>>>(histE, pH16);
    tbase_kernel<<<BATCH / 64, 256, tb_smem>>>(
        iid, itemE, Wproj, pWb, ab1, pT16, pBase);

    // K1: attention + feature concat
    attn_kernel<<<BATCH, 256, attn_smem>>>(
        uid, iid, cid, did, udense, idense, hseq,
        userE, itemE, catE, durE, pH16,
        pT16, pBase, pPt, pW3t, pAW2t, aW3, ab3, ab2, pS, pSh);

    // K2a: eh = relu(S @ eW1 + eb1), fp16 out
    hgemm_bias_relu<true><<<dim3(EHID / TBN, BATCH / TBM, NEXP), 256, HGEMM_SMEM>>>(
        pSh, pW1t, eb1, pEh,
        BATCH, EHID,
        (size_t)0, (size_t)EHID * KPAD, (size_t)EHID, (size_t)BATCH * EHID);

    // K2b: eo = relu(eh @ eW2 + eb2), fp16 out
    hgemm_bias_relu<true><<<dim3(EOUT / TBN, BATCH / TBM, NEXP), 256, HGEMM_SMEM>>>(
        pEh, pW2t, eb2, pEo,
        BATCH, EOUT,
        (size_t)BATCH * EHID, (size_t)EOUT * KPAD, (size_t)EOUT, (size_t)BATCH * EOUT);

    // K3: gates + mix + towers + sigmoid
    head_kernel<<<BATCH / 4, 256>>>(
        pS, pEo, gW, gb, tW1, tb1, tW2, tb2, tW3, tb3, out);
}